// round 16
// baseline (speedup 1.0000x reference)
#include <cuda_runtime.h>
#include <cuda_fp16.h>
#include <cstdint>

#define NN   4096
#define BB   16
#define NB   256      // nodes per batch
#define ND   9        // NUM_DEG
#define FF   128
#define MCH  1152     // 9*128
#define NFREQ 64
#define SZSLAB (BB * NB * NB)

// ---------------- scratch (static device memory; no allocations) ------------
__device__ __half g_q[NN * MCH];
__device__ __half g_k[NN * MCH];
__device__ __half g_v[NN * MCH];
__device__ __half g_csh[NN * 3 * 32 * 8];   // [node][axis][fpair]{c0c0c1c1 s0s0s1s1}
__device__ __half g_wt[9 * FF * FF];        // W transposed: [z][n][k] fp16
__device__ __half g_Spart[9u * SZSLAB];     // 9 partial slabs (fp16)
__device__ __half g_S[SZSLAB];              // reduced S (fp16)

// ---------------- helpers ------------------------------------------------------
__device__ __forceinline__ uint32_t cvsm(const void* p) {
    return (uint32_t)__cvta_generic_to_shared(p);
}
__device__ __forceinline__ void ldsm4(uint32_t* r, uint32_t addr) {
    asm volatile("ldmatrix.sync.aligned.m8n8.x4.shared.b16 {%0,%1,%2,%3}, [%4];"
                 : "=r"(r[0]), "=r"(r[1]), "=r"(r[2]), "=r"(r[3])
                 : "r"(addr));
}
__device__ __forceinline__ void mma16816h(float* d, const uint32_t* a,
                                          uint32_t b0, uint32_t b1) {
    asm volatile(
        "mma.sync.aligned.m16n8k16.row.col.f32.f16.f16.f32 "
        "{%0,%1,%2,%3}, {%4,%5,%6,%7}, {%8,%9}, {%0,%1,%2,%3};"
        : "+f"(d[0]), "+f"(d[1]), "+f"(d[2]), "+f"(d[3])
        : "r"(a[0]), "r"(a[1]), "r"(a[2]), "r"(a[3]), "r"(b0), "r"(b1));
}

// ---- fp16 single-term mma over staged chunk: A at base, B at base+ARR ----
template <int PITCH, int NK16>
__device__ __forceinline__ void mma_chunk_h(
    const __half* base, float acc[2][8][4],
    int wm, int wn, int at_r, int at_k, int bt_n, int bt_k) {
    const int ARR = 128 * PITCH;
    const __half* A = base;
    const __half* B = base + ARR;
#pragma unroll
    for (int k16 = 0; k16 < NK16; k16++) {
        int kc = k16 * 16 + at_k;
        uint32_t ah[2][4];
#pragma unroll
        for (int mt = 0; mt < 2; mt++) {
            int row = wm * 32 + mt * 16 + at_r;
            ldsm4(ah[mt], cvsm(A + row * PITCH + kc));
        }
        int kcb = k16 * 16 + bt_k;
#pragma unroll
        for (int np = 0; np < 4; np++) {
            int n = wn * 64 + np * 16 + bt_n;
            uint32_t bb[4];
            ldsm4(bb, cvsm(B + n * PITCH + kcb));
#pragma unroll
            for (int mt = 0; mt < 2; mt++) {
#pragma unroll
                for (int nt = 0; nt < 2; nt++) {
                    mma16816h(acc[mt][np * 2 + nt], ah[mt],
                              bb[nt * 2], bb[nt * 2 + 1]);
                }
            }
        }
    }
}

#define SPITCH 40
#define SARR   (128 * SPITCH)
#define PO_SMEM (2 * 2 * SARR * 2)   // 40960 B

// ---------------- kernel: packed fp16 cos/sin tables ---------------------------
__global__ void k_cs(const float* __restrict__ pos) {
    int idx = blockIdx.x * 256 + threadIdx.x;   // (n*3+a)*32 + j
    if (idx >= NN * 3 * 32) return;
    int j = idx & 31;
    int a = (idx >> 5) % 3;
    int n = idx / 96;
    float th0 = (8.0f / (63.0f * 10.0f)) * (float)(2 * j);
    float th1 = (8.0f / (63.0f * 10.0f)) * (float)(2 * j + 1);
    float pa = pos[n * 3 + a];
    float s0, c0, s1, c1;
    sincosf(pa * th0, &s0, &c0);
    sincosf(pa * th1, &s1, &c1);
    __half2* e = (__half2*)(g_csh + (size_t)idx * 8);
    e[0] = __floats2half2_rn(c0, c0);
    e[1] = __floats2half2_rn(c1, c1);
    e[2] = __floats2half2_rn(s0, s0);
    e[3] = __floats2half2_rn(s1, s1);
}

// ---------------- kernel: pre-transpose W -> fp16 [z][n][k] --------------------
__global__ void k_prew(const float* __restrict__ Wq,
                       const float* __restrict__ Wk,
                       const float* __restrict__ Wv) {
    int idx = blockIdx.x * 256 + threadIdx.x;   // (z, n, k2)
    if (idx >= 9 * 128 * 64) return;
    int k2 = idx & 63;
    int n  = (idx >> 6) & 127;
    int z  = idx >> 13;
    int p = z / 3, l = z % 3;
    const float* W = (p == 0 ? Wq : (p == 1 ? Wk : Wv)) + l * FF * FF;
    float w0 = W[(2 * k2) * 128 + n];
    float w1 = W[(2 * k2 + 1) * 128 + n];
    *(__half2*)(g_wt + ((size_t)z * 128 + n) * 128 + 2 * k2) =
        __floats2half2_rn(w0, w1);
}

// ---------------- kernel: q/k/v projections via fp16 mma.sync ------------------
__global__ void __launch_bounds__(256, 2)
k_proj(const float* __restrict__ X,
       const float* __restrict__ bq, const float* __restrict__ bk,
       const float* __restrict__ bv) {
    extern __shared__ unsigned char smraw[];
    __half* smh = (__half*)smraw;

    int z = blockIdx.z;
    int p = z / 3, l = z % 3;
    const int cnt = (l == 0) ? 1 : (l == 1 ? 3 : 5);
    const int m0  = (l == 0) ? 0 : (l == 1 ? 1 : 4);
    int ntiles = (NN * cnt) >> 7;
    if ((int)blockIdx.x >= ntiles) return;

    const __half* Wt  = g_wt + (size_t)z * FF * FF;
    const float* bias = (p == 0 ? bq : (p == 1 ? bk : bv));
    __half* dst = (p == 0 ? g_q : (p == 1 ? g_k : g_v));

    int row0 = blockIdx.x * 128;
    int tid = threadIdx.x;
    int wid = tid >> 5, lane = tid & 31;
    int wm = wid & 3, wn = wid >> 2;
    int kq = tid & 7, rr = tid >> 3;
    int brow = tid & 127, bko = (tid >> 7) * 8;

    const float* arow[4];
#pragma unroll
    for (int i = 0; i < 4; i++) {
        int rg = row0 + rr + i * 32;
        int node = rg / cnt, mi = rg - node * cnt;
        arow[i] = X + ((size_t)node * ND + (m0 + mi)) * FF;
    }

    float acc[2][8][4];
#pragma unroll
    for (int mt = 0; mt < 2; mt++)
#pragma unroll
        for (int nt = 0; nt < 8; nt++)
#pragma unroll
            for (int e = 0; e < 4; e++) acc[mt][nt][e] = 0.0f;

    int at_r = (lane & 7) + ((lane >> 3) & 1) * 8;
    int at_k = (lane >> 4) * 8;
    int bt_n = (lane & 7) + ((lane & 16) ? 8 : 0);
    int bt_k = ((lane >> 3) & 1) * 8;

    auto stage = [&](int c, int st) {
        int f0 = c * 32;
        __half* Ah = smh + st * 2 * SARR;
#pragma unroll
        for (int i = 0; i < 4; i++) {
            int r = rr + i * 32;
            float4 v = *(const float4*)(arow[i] + f0 + kq * 4);
            union { __half2 h2[2]; uint2 u; } pk;
            pk.h2[0] = __floats2half2_rn(v.x, v.y);
            pk.h2[1] = __floats2half2_rn(v.z, v.w);
            *(uint2*)(Ah + r * SPITCH + kq * 4) = pk.u;
        }
        __half* Bh = Ah + SARR;
#pragma unroll
        for (int it = 0; it < 2; it++) {
            int ko = bko + it * 16;
            *(uint4*)(Bh + brow * SPITCH + ko) =
                *(const uint4*)(Wt + (size_t)brow * 128 + f0 + ko);
        }
    };

    stage(0, 0);
    __syncthreads();
    for (int c = 0; c < 4; c++) {
        int st = c & 1;
        if (c + 1 < 4) stage(c + 1, st ^ 1);
        mma_chunk_h<SPITCH, 2>(smh + st * 2 * SARR, acc, wm, wn, at_r, at_k, bt_n, bt_k);
        __syncthreads();
    }

    int tr = lane >> 2, tc = (lane & 3) * 2;
#pragma unroll
    for (int mt = 0; mt < 2; mt++) {
#pragma unroll
        for (int half = 0; half < 2; half++) {
            int rgl = row0 + wm * 32 + mt * 16 + tr + half * 8;
            int node = rgl / cnt, mi = rgl - node * cnt;
            size_t obase = (size_t)node * MCH + (m0 + mi) * FF;
#pragma unroll
            for (int nt = 0; nt < 8; nt++) {
                int col = wn * 64 + nt * 8 + tc;
                float d0 = acc[mt][nt][half * 2 + 0];
                float d1 = acc[mt][nt][half * 2 + 1];
                if (l == 0) { d0 += bias[col]; d1 += bias[col + 1]; }
                *(__half2*)(dst + obase + col) = __floats2half2_rn(d0, d1);
            }
        }
    }
}

// ---------------- kernel: score partials, 64x128 CTA, 32x32 warp tiles --------
// grid (4,2,144): x = i-tile of 64 rows, y = j-tile of 128 cols.
// 8 warps: wm = wid&1 (2 x 32 rows), wn = wid>>1 (4 x 32 cols). occ 3.
#define KP2 72
#define KS_A (64 * KP2)
#define KS_B (128 * KP2)
#define KS_STAGE (KS_A + KS_B)
#define KS_SMEM (2 * KS_STAGE * 2)   // 55296 B

__global__ void __launch_bounds__(256, 3)
k_score() {
    extern __shared__ unsigned char smraw[];
    __half* smh = (__half*)smraw;

    int zz = blockIdx.z;
    int b = zz / 9, sp = zz - b * 9;
    int a = sp / 3, mc = sp - a * 3;
    int nb_i = b * NB + blockIdx.x * 64;
    int nb_j = b * NB + blockIdx.y * 128;
    int tid = threadIdx.x;
    int wid = tid >> 5, lane = tid & 31;
    int wm = wid & 1, wn = wid >> 1;
    int kq = tid & 7, rr = tid >> 3;
    int chbase = mc * 384;

    float acc[2][4][4];
#pragma unroll
    for (int mt = 0; mt < 2; mt++)
#pragma unroll
        for (int nt = 0; nt < 4; nt++)
#pragma unroll
            for (int e = 0; e < 4; e++) acc[mt][nt][e] = 0.0f;

    int at_r = (lane & 7) + ((lane >> 3) & 1) * 8;
    int at_k = (lane >> 4) * 8;
    int bt_n = (lane & 7) + ((lane & 16) ? 8 : 0);
    int bt_k = ((lane >> 3) & 1) * 8;

    uint2 rawq[2], rawk[4];

    auto loadraw = [&](int c) {
        int ch = chbase + c * 32 + kq * 4;
#pragma unroll
        for (int i = 0; i < 2; i++) {
            int node = nb_i + rr + i * 32;
            rawq[i] = *(const uint2*)(g_q + (size_t)node * MCH + ch);
        }
#pragma unroll
        for (int i = 0; i < 4; i++) {
            int node = nb_j + rr + i * 32;
            rawk[i] = *(const uint2*)(g_k + (size_t)node * MCH + ch);
        }
    };

    auto cvtsts = [&](int c, int st) {
        int chl = c * 32 + kq * 4;
        int j = (chl & 127) >> 2;
        __half* DA = smh + st * KS_STAGE;
        __half* DB = DA + KS_A;
#pragma unroll
        for (int i = 0; i < 2; i++) {
            int r = rr + i * 32;
            int node = nb_i + r;
            union { __half2 h2[4]; uint4 u; } tb;
            tb.u = *(const uint4*)(g_csh + (((size_t)node * 3 + a) * 32 + j) * 8);
            union { __half2 h2[2]; uint2 u; } rw, o;
            rw.u = rawq[i];
            o.h2[0] = __hmul2(rw.h2[0], tb.h2[0]);
            o.h2[1] = __hmul2(rw.h2[1], tb.h2[1]);
            *(uint2*)(DA + r * KP2 + kq * 4) = o.u;
            o.h2[0] = __hmul2(rw.h2[0], tb.h2[2]);
            o.h2[1] = __hmul2(rw.h2[1], tb.h2[3]);
            *(uint2*)(DA + r * KP2 + 32 + kq * 4) = o.u;
        }
#pragma unroll
        for (int i = 0; i < 4; i++) {
            int r = rr + i * 32;
            int node = nb_j + r;
            union { __half2 h2[4]; uint4 u; } tb;
            tb.u = *(const uint4*)(g_csh + (((size_t)node * 3 + a) * 32 + j) * 8);
            union { __half2 h2[2]; uint2 u; } rw, o;
            rw.u = rawk[i];
            o.h2[0] = __hmul2(rw.h2[0], tb.h2[0]);
            o.h2[1] = __hmul2(rw.h2[1], tb.h2[1]);
            *(uint2*)(DB + r * KP2 + kq * 4) = o.u;
            o.h2[0] = __hmul2(rw.h2[0], tb.h2[2]);
            o.h2[1] = __hmul2(rw.h2[1], tb.h2[3]);
            *(uint2*)(DB + r * KP2 + 32 + kq * 4) = o.u;
        }
    };

    auto mma_st = [&](int st) {
        const __half* A = smh + st * KS_STAGE;
        const __half* B = A + KS_A;
#pragma unroll
        for (int k16 = 0; k16 < 4; k16++) {
            int kc = k16 * 16 + at_k;
            uint32_t ah[2][4];
#pragma unroll
            for (int mt = 0; mt < 2; mt++) {
                int row = wm * 32 + mt * 16 + at_r;
                ldsm4(ah[mt], cvsm(A + row * KP2 + kc));
            }
            int kcb = k16 * 16 + bt_k;
#pragma unroll
            for (int np = 0; np < 2; np++) {
                int n = wn * 32 + np * 16 + bt_n;
                uint32_t bb[4];
                ldsm4(bb, cvsm(B + n * KP2 + kcb));
#pragma unroll
                for (int mt = 0; mt < 2; mt++) {
#pragma unroll
                    for (int nt = 0; nt < 2; nt++) {
                        mma16816h(acc[mt][np * 2 + nt], ah[mt],
                                  bb[nt * 2], bb[nt * 2 + 1]);
                    }
                }
            }
        }
    };

    loadraw(0);
    cvtsts(0, 0);
    loadraw(1);
    __syncthreads();
    for (int c = 0; c < 12; c++) {
        int st = c & 1;
        if (c + 1 < 12) cvtsts(c + 1, st ^ 1);
        if (c + 2 < 12) loadraw(c + 2);
        mma_st(st);
        __syncthreads();
    }

    // epilogue -> fp16 partial slab
    size_t base = ((size_t)sp * BB + b) * (NB * NB);
    int gr = blockIdx.x * 64 + wm * 32;
    int gc = blockIdx.y * 128 + wn * 32;
    int tr = lane >> 2, tc2 = (lane & 3) * 2;
#pragma unroll
    for (int mt = 0; mt < 2; mt++) {
#pragma unroll
        for (int nt = 0; nt < 4; nt++) {
            int r0 = gr + mt * 16 + tr;
            int cc = gc + nt * 8 + tc2;
            *(__half2*)(g_Spart + base + (size_t)r0 * NB + cc) =
                __floats2half2_rn(acc[mt][nt][0], acc[mt][nt][1]);
            *(__half2*)(g_Spart + base + (size_t)(r0 + 8) * NB + cc) =
                __floats2half2_rn(acc[mt][nt][2], acc[mt][nt][3]);
        }
    }
}

// ---------------- kernel: slab reduce (fp16 in, fp32 sum, fp16 out) -----------
__global__ void k_reduceS() {
    int i = (blockIdx.x * 256 + threadIdx.x) * 8;
    if (i >= SZSLAB) return;
    float s[8];
#pragma unroll
    for (int e = 0; e < 8; e++) s[e] = 0.0f;
#pragma unroll
    for (int sl = 0; sl < 9; sl++) {
        union { __half2 h2[4]; uint4 u; } t;
        t.u = *(const uint4*)(g_Spart + (size_t)sl * SZSLAB + i);
#pragma unroll
        for (int e = 0; e < 4; e++) {
            float2 v = __half22float2(t.h2[e]);
            s[e * 2 + 0] += v.x;
            s[e * 2 + 1] += v.y;
        }
    }
    union { __half2 h2[4]; uint4 u; } o;
#pragma unroll
    for (int e = 0; e < 4; e++)
        o.h2[e] = __floats2half2_rn(s[e * 2] * (1.0f / 3.0f),
                                    s[e * 2 + 1] * (1.0f / 3.0f));
    *(uint4*)(g_S + i) = o.u;
}

// ---------------- kernel: out = Sbar @ V (+mask) via fp16 mma.sync -------------
__global__ void __launch_bounds__(256, 2)
k_out(const int* __restrict__ bseg, const int* __restrict__ gmask,
      float* __restrict__ out) {
    extern __shared__ unsigned char smraw[];
    __half* smh = (__half*)smraw;

    int b = blockIdx.z;
    int r0 = blockIdx.x * 128;
    int d0 = blockIdx.y * 128;
    int tid = threadIdx.x;
    int wid = tid >> 5, lane = tid & 31;
    int wm = wid & 3, wn = wid >> 2;
    int kq = tid & 7, rr = tid >> 3;
    int kk = tid & 31, ng = tid >> 5;

    float acc[2][8][4];
#pragma unroll
    for (int mt = 0; mt < 2; mt++)
#pragma unroll
        for (int nt = 0; nt < 8; nt++)
#pragma unroll
            for (int e = 0; e < 4; e++) acc[mt][nt][e] = 0.0f;

    int at_r = (lane & 7) + ((lane >> 3) & 1) * 8;
    int at_k = (lane >> 4) * 8;
    int bt_n = (lane & 7) + ((lane & 16) ? 8 : 0);
    int bt_k = ((lane >> 3) & 1) * 8;

    auto stage = [&](int c, int st) {
        int j0 = c * 32;
        __half* Ah = smh + st * 2 * SARR;
#pragma unroll
        for (int i = 0; i < 4; i++) {
            int r = rr + i * 32;
            *(uint2*)(Ah + r * SPITCH + kq * 4) =
                *(const uint2*)(g_S + ((size_t)b * NB + r0 + r) * NB + j0 + kq * 4);
        }
        __half* Bh = Ah + SARR;
#pragma unroll
        for (int j = 0; j < 4; j++) {
            int n0 = ng * 16 + j * 4;
            union { __half h[4]; uint2 u; } rawv;
            rawv.u = *(const uint2*)(g_v + ((size_t)(b * NB + j0 + kk)) * MCH + d0 + n0);
#pragma unroll
            for (int e = 0; e < 4; e++)
                Bh[(n0 + e) * SPITCH + kk] = rawv.h[e];
        }
    };

    stage(0, 0);
    __syncthreads();
    for (int c = 0; c < 8; c++) {
        int st = c & 1;
        if (c + 1 < 8) stage(c + 1, st ^ 1);
        mma_chunk_h<SPITCH, 2>(smh + st * 2 * SARR, acc, wm, wn, at_r, at_k, bt_n, bt_k);
        __syncthreads();
    }

    int tr = lane >> 2, tc = (lane & 3) * 2;
#pragma unroll
    for (int mt = 0; mt < 2; mt++) {
#pragma unroll
        for (int half = 0; half < 2; half++) {
            int node = b * NB + r0 + wm * 32 + mt * 16 + tr + half * 8;
            bool mk = gmask[bseg[node]] != 0;
#pragma unroll
            for (int nt = 0; nt < 8; nt++) {
                int col = wn * 64 + nt * 8 + tc;
                float o0 = mk ? acc[mt][nt][half * 2 + 0] : 0.0f;
                float o1 = mk ? acc[mt][nt][half * 2 + 1] : 0.0f;
                *(float2*)(out + (size_t)node * MCH + d0 + col) = make_float2(o0, o1);
            }
        }
    }
}

// ---------------- launcher ----------------------------------------------------
extern "C" void kernel_launch(void* const* d_in, const int* in_sizes, int n_in,
                              void* d_out, int out_size) {
    const float* X   = (const float*)d_in[0];
    const float* pos = (const float*)d_in[1];
    const int* bseg  = (const int*)d_in[2];
    const int* gmask = (const int*)d_in[3];   // bool -> int32 in harness
    const float* Wq = (const float*)d_in[4];
    const float* bq = (const float*)d_in[5];
    const float* Wk = (const float*)d_in[6];
    const float* bk = (const float*)d_in[7];
    const float* Wv = (const float*)d_in[8];
    const float* bv = (const float*)d_in[9];
    float* out = (float*)d_out;

    cudaFuncSetAttribute(k_proj,  cudaFuncAttributeMaxDynamicSharedMemorySize, PO_SMEM);
    cudaFuncSetAttribute(k_score, cudaFuncAttributeMaxDynamicSharedMemorySize, KS_SMEM);
    cudaFuncSetAttribute(k_out,   cudaFuncAttributeMaxDynamicSharedMemorySize, PO_SMEM);

    k_cs<<<(NN * 3 * 32 + 255) / 256, 256>>>(pos);
    k_prew<<<(9 * 128 * 64 + 255) / 256, 256>>>(Wq, Wk, Wv);
    k_proj<<<dim3(160, 1, 9), 256, PO_SMEM>>>(X, bq, bk, bv);
    k_score<<<dim3(4, 2, BB * 9), 256, KS_SMEM>>>();
    k_reduceS<<<SZSLAB / 2048, 256>>>();
    k_out<<<dim3(2, 9, BB), 256, PO_SMEM>>>(bseg, gmask, out);
}

// round 17
// speedup vs baseline: 1.1816x; 1.1816x over previous
#include <cuda_runtime.h>
#include <cuda_fp16.h>
#include <cstdint>

#define NN   4096
#define BB   16
#define NB   256      // nodes per batch
#define ND   9        // NUM_DEG
#define FF   128
#define MCH  1152     // 9*128
#define NFREQ 64
#define SZSLAB (BB * NB * NB)

// ---------------- scratch (static device memory; no allocations) ------------
__device__ __half g_q[NN * MCH];
__device__ __half g_k[NN * MCH];
__device__ __half g_v[NN * MCH];
__device__ __half g_csh[NN * 3 * 32 * 8];   // [node][axis][fpair]{c0c0c1c1 s0s0s1s1}
__device__ __half g_wt[9 * FF * FF];        // W transposed: [z][n][k] fp16
__device__ __half g_Spart[9u * SZSLAB];     // 9 partial slabs (fp16)
__device__ __half g_S[SZSLAB];              // reduced S (fp16)

// ---------------- helpers ------------------------------------------------------
__device__ __forceinline__ uint32_t cvsm(const void* p) {
    return (uint32_t)__cvta_generic_to_shared(p);
}
__device__ __forceinline__ void ldsm4(uint32_t* r, uint32_t addr) {
    asm volatile("ldmatrix.sync.aligned.m8n8.x4.shared.b16 {%0,%1,%2,%3}, [%4];"
                 : "=r"(r[0]), "=r"(r[1]), "=r"(r[2]), "=r"(r[3])
                 : "r"(addr));
}
__device__ __forceinline__ void mma16816h(float* d, const uint32_t* a,
                                          uint32_t b0, uint32_t b1) {
    asm volatile(
        "mma.sync.aligned.m16n8k16.row.col.f32.f16.f16.f32 "
        "{%0,%1,%2,%3}, {%4,%5,%6,%7}, {%8,%9}, {%0,%1,%2,%3};"
        : "+f"(d[0]), "+f"(d[1]), "+f"(d[2]), "+f"(d[3])
        : "r"(a[0]), "r"(a[1]), "r"(a[2]), "r"(a[3]), "r"(b0), "r"(b1));
}

// ---- fp16 single-term mma over staged chunk: A at base, B at base+ARR ----
template <int PITCH, int NK16>
__device__ __forceinline__ void mma_chunk_h(
    const __half* base, float acc[2][8][4],
    int wm, int wn, int at_r, int at_k, int bt_n, int bt_k) {
    const int ARR = 128 * PITCH;
    const __half* A = base;
    const __half* B = base + ARR;
#pragma unroll
    for (int k16 = 0; k16 < NK16; k16++) {
        int kc = k16 * 16 + at_k;
        uint32_t ah[2][4];
#pragma unroll
        for (int mt = 0; mt < 2; mt++) {
            int row = wm * 32 + mt * 16 + at_r;
            ldsm4(ah[mt], cvsm(A + row * PITCH + kc));
        }
        int kcb = k16 * 16 + bt_k;
#pragma unroll
        for (int np = 0; np < 4; np++) {
            int n = wn * 64 + np * 16 + bt_n;
            uint32_t bb[4];
            ldsm4(bb, cvsm(B + n * PITCH + kcb));
#pragma unroll
            for (int mt = 0; mt < 2; mt++) {
#pragma unroll
                for (int nt = 0; nt < 2; nt++) {
                    mma16816h(acc[mt][np * 2 + nt], ah[mt],
                              bb[nt * 2], bb[nt * 2 + 1]);
                }
            }
        }
    }
}

#define SPITCH 40
#define SARR   (128 * SPITCH)
#define PO_SMEM (2 * 2 * SARR * 2)   // 40960 B

// ---------------- kernel: prep (cos/sin tables + W transpose) -----------------
__global__ void k_pre(const float* __restrict__ pos,
                      const float* __restrict__ Wq,
                      const float* __restrict__ Wk,
                      const float* __restrict__ Wv) {
    int idx = blockIdx.x * 256 + threadIdx.x;
    const int NCS = NN * 3 * 32;
    if (idx < NCS) {
        int j = idx & 31;
        int a = (idx >> 5) % 3;
        int n = idx / 96;
        float th0 = (8.0f / (63.0f * 10.0f)) * (float)(2 * j);
        float th1 = (8.0f / (63.0f * 10.0f)) * (float)(2 * j + 1);
        float pa = pos[n * 3 + a];
        float s0, c0, s1, c1;
        sincosf(pa * th0, &s0, &c0);
        sincosf(pa * th1, &s1, &c1);
        __half2* e = (__half2*)(g_csh + (size_t)idx * 8);
        e[0] = __floats2half2_rn(c0, c0);
        e[1] = __floats2half2_rn(c1, c1);
        e[2] = __floats2half2_rn(s0, s0);
        e[3] = __floats2half2_rn(s1, s1);
    } else {
        int wi = idx - NCS;
        if (wi >= 9 * 128 * 64) return;
        int k2 = wi & 63;
        int n  = (wi >> 6) & 127;
        int z  = wi >> 13;
        int p = z / 3, l = z % 3;
        const float* W = (p == 0 ? Wq : (p == 1 ? Wk : Wv)) + l * FF * FF;
        float w0 = W[(2 * k2) * 128 + n];
        float w1 = W[(2 * k2 + 1) * 128 + n];
        *(__half2*)(g_wt + ((size_t)z * 128 + n) * 128 + 2 * k2) =
            __floats2half2_rn(w0, w1);
    }
}

// ---------------- kernel: q/k/v projections via fp16 mma.sync ------------------
__global__ void __launch_bounds__(256, 2)
k_proj(const float* __restrict__ X,
       const float* __restrict__ bq, const float* __restrict__ bk,
       const float* __restrict__ bv) {
    extern __shared__ unsigned char smraw[];
    __half* smh = (__half*)smraw;

    int z = blockIdx.z;
    int p = z / 3, l = z % 3;
    const int cnt = (l == 0) ? 1 : (l == 1 ? 3 : 5);
    const int m0  = (l == 0) ? 0 : (l == 1 ? 1 : 4);
    int ntiles = (NN * cnt) >> 7;
    if ((int)blockIdx.x >= ntiles) return;

    const __half* Wt  = g_wt + (size_t)z * FF * FF;
    const float* bias = (p == 0 ? bq : (p == 1 ? bk : bv));
    __half* dst = (p == 0 ? g_q : (p == 1 ? g_k : g_v));

    int row0 = blockIdx.x * 128;
    int tid = threadIdx.x;
    int wid = tid >> 5, lane = tid & 31;
    int wm = wid & 3, wn = wid >> 2;
    int kq = tid & 7, rr = tid >> 3;
    int brow = tid & 127, bko = (tid >> 7) * 8;

    const float* arow[4];
#pragma unroll
    for (int i = 0; i < 4; i++) {
        int rg = row0 + rr + i * 32;
        int node = rg / cnt, mi = rg - node * cnt;
        arow[i] = X + ((size_t)node * ND + (m0 + mi)) * FF;
    }

    float acc[2][8][4];
#pragma unroll
    for (int mt = 0; mt < 2; mt++)
#pragma unroll
        for (int nt = 0; nt < 8; nt++)
#pragma unroll
            for (int e = 0; e < 4; e++) acc[mt][nt][e] = 0.0f;

    int at_r = (lane & 7) + ((lane >> 3) & 1) * 8;
    int at_k = (lane >> 4) * 8;
    int bt_n = (lane & 7) + ((lane & 16) ? 8 : 0);
    int bt_k = ((lane >> 3) & 1) * 8;

    auto stage = [&](int c, int st) {
        int f0 = c * 32;
        __half* Ah = smh + st * 2 * SARR;
#pragma unroll
        for (int i = 0; i < 4; i++) {
            int r = rr + i * 32;
            float4 v = *(const float4*)(arow[i] + f0 + kq * 4);
            union { __half2 h2[2]; uint2 u; } pk;
            pk.h2[0] = __floats2half2_rn(v.x, v.y);
            pk.h2[1] = __floats2half2_rn(v.z, v.w);
            *(uint2*)(Ah + r * SPITCH + kq * 4) = pk.u;
        }
        __half* Bh = Ah + SARR;
#pragma unroll
        for (int it = 0; it < 2; it++) {
            int ko = bko + it * 16;
            *(uint4*)(Bh + brow * SPITCH + ko) =
                *(const uint4*)(Wt + (size_t)brow * 128 + f0 + ko);
        }
    };

    stage(0, 0);
    __syncthreads();
    for (int c = 0; c < 4; c++) {
        int st = c & 1;
        if (c + 1 < 4) stage(c + 1, st ^ 1);
        mma_chunk_h<SPITCH, 2>(smh + st * 2 * SARR, acc, wm, wn, at_r, at_k, bt_n, bt_k);
        __syncthreads();
    }

    int tr = lane >> 2, tc = (lane & 3) * 2;
#pragma unroll
    for (int mt = 0; mt < 2; mt++) {
#pragma unroll
        for (int half = 0; half < 2; half++) {
            int rgl = row0 + wm * 32 + mt * 16 + tr + half * 8;
            int node = rgl / cnt, mi = rgl - node * cnt;
            size_t obase = (size_t)node * MCH + (m0 + mi) * FF;
#pragma unroll
            for (int nt = 0; nt < 8; nt++) {
                int col = wn * 64 + nt * 8 + tc;
                float d0 = acc[mt][nt][half * 2 + 0];
                float d1 = acc[mt][nt][half * 2 + 1];
                if (l == 0) { d0 += bias[col]; d1 += bias[col + 1]; }
                *(__half2*)(dst + obase + col) = __floats2half2_rn(d0, d1);
            }
        }
    }
}

// ---------------- kernel: score partials, software-pipelined fp16 mma ---------
#define KP2 72
#define KA2 (128 * KP2)
#define KS_SMEM (2 * 2 * KA2 * 2)   // 73728 B

__global__ void __launch_bounds__(256, 2)
k_score() {
    extern __shared__ unsigned char smraw[];
    __half* smh = (__half*)smraw;

    int zz = blockIdx.z;
    int b = zz / 9, sp = zz - b * 9;
    int a = sp / 3, mc = sp - a * 3;
    int nb_i = b * NB + blockIdx.x * 128;
    int nb_j = b * NB + blockIdx.y * 128;
    int tid = threadIdx.x;
    int wid = tid >> 5, lane = tid & 31;
    int wm = wid & 3, wn = wid >> 2;
    int kq = tid & 7, rr = tid >> 3;
    int chbase = mc * 384;

    float acc[2][8][4];
#pragma unroll
    for (int mt = 0; mt < 2; mt++)
#pragma unroll
        for (int nt = 0; nt < 8; nt++)
#pragma unroll
            for (int e = 0; e < 4; e++) acc[mt][nt][e] = 0.0f;

    int at_r = (lane & 7) + ((lane >> 3) & 1) * 8;
    int at_k = (lane >> 4) * 8;
    int bt_n = (lane & 7) + ((lane & 16) ? 8 : 0);
    int bt_k = ((lane >> 3) & 1) * 8;

    uint2 raw[8];

    auto loadraw = [&](int c) {
        int ch = chbase + c * 32 + kq * 4;
#pragma unroll
        for (int pass = 0; pass < 2; pass++) {
            const __half* src = pass == 0 ? g_q : g_k;
            int nb = pass == 0 ? nb_i : nb_j;
#pragma unroll
            for (int i = 0; i < 4; i++) {
                int node = nb + rr + i * 32;
                raw[pass * 4 + i] = *(const uint2*)(src + (size_t)node * MCH + ch);
            }
        }
    };

    auto cvtsts = [&](int c, int st) {
        int chl = c * 32 + kq * 4;
        int j = (chl & 127) >> 2;   // freq-pair index
#pragma unroll
        for (int pass = 0; pass < 2; pass++) {
            int nb = pass == 0 ? nb_i : nb_j;
            __half* D = smh + st * 2 * KA2 + pass * KA2;
#pragma unroll
            for (int i = 0; i < 4; i++) {
                int r = rr + i * 32;
                int node = nb + r;
                union { __half2 h2[4]; uint4 u; } tb;
                tb.u = *(const uint4*)(g_csh + (((size_t)node * 3 + a) * 32 + j) * 8);
                union { __half2 h2[2]; uint2 u; } rw;
                rw.u = raw[pass * 4 + i];
                union { __half2 h2[2]; uint2 u; } o;
                o.h2[0] = __hmul2(rw.h2[0], tb.h2[0]);
                o.h2[1] = __hmul2(rw.h2[1], tb.h2[1]);
                *(uint2*)(D + r * KP2 + kq * 4) = o.u;
                o.h2[0] = __hmul2(rw.h2[0], tb.h2[2]);
                o.h2[1] = __hmul2(rw.h2[1], tb.h2[3]);
                *(uint2*)(D + r * KP2 + 32 + kq * 4) = o.u;
            }
        }
    };

    loadraw(0);
    cvtsts(0, 0);
    loadraw(1);
    __syncthreads();
    for (int c = 0; c < 12; c++) {
        int st = c & 1;
        if (c + 1 < 12) cvtsts(c + 1, st ^ 1);
        if (c + 2 < 12) loadraw(c + 2);
        mma_chunk_h<KP2, 4>(smh + st * 2 * KA2, acc, wm, wn, at_r, at_k, bt_n, bt_k);
        __syncthreads();
    }

    // epilogue -> fp16 partial slab
    size_t base = ((size_t)sp * BB + b) * (NB * NB);
    int gr = blockIdx.x * 128 + wm * 32;
    int gc = blockIdx.y * 128 + wn * 64;
    int tr = lane >> 2, tc2 = (lane & 3) * 2;
#pragma unroll
    for (int mt = 0; mt < 2; mt++) {
#pragma unroll
        for (int nt = 0; nt < 8; nt++) {
            int r0 = gr + mt * 16 + tr;
            int cc = gc + nt * 8 + tc2;
            *(__half2*)(g_Spart + base + (size_t)r0 * NB + cc) =
                __floats2half2_rn(acc[mt][nt][0], acc[mt][nt][1]);
            *(__half2*)(g_Spart + base + (size_t)(r0 + 8) * NB + cc) =
                __floats2half2_rn(acc[mt][nt][2], acc[mt][nt][3]);
        }
    }
}

// ---------------- kernel: slab reduce (fp16 in, fp32 sum, fp16 out) -----------
__global__ void k_reduceS() {
    int i = (blockIdx.x * 256 + threadIdx.x) * 8;
    if (i >= SZSLAB) return;
    float s[8];
#pragma unroll
    for (int e = 0; e < 8; e++) s[e] = 0.0f;
#pragma unroll
    for (int sl = 0; sl < 9; sl++) {
        union { __half2 h2[4]; uint4 u; } t;
        t.u = *(const uint4*)(g_Spart + (size_t)sl * SZSLAB + i);
#pragma unroll
        for (int e = 0; e < 4; e++) {
            float2 v = __half22float2(t.h2[e]);
            s[e * 2 + 0] += v.x;
            s[e * 2 + 1] += v.y;
        }
    }
    union { __half2 h2[4]; uint4 u; } o;
#pragma unroll
    for (int e = 0; e < 4; e++)
        o.h2[e] = __floats2half2_rn(s[e * 2] * (1.0f / 3.0f),
                                    s[e * 2 + 1] * (1.0f / 3.0f));
    *(uint4*)(g_S + i) = o.u;
}

// ---------------- kernel: out = Sbar @ V (+mask) via fp16 mma.sync -------------
__global__ void __launch_bounds__(256, 2)
k_out(const int* __restrict__ bseg, const int* __restrict__ gmask,
      float* __restrict__ out) {
    extern __shared__ unsigned char smraw[];
    __half* smh = (__half*)smraw;

    int b = blockIdx.z;
    int r0 = blockIdx.x * 128;
    int d0 = blockIdx.y * 128;
    int tid = threadIdx.x;
    int wid = tid >> 5, lane = tid & 31;
    int wm = wid & 3, wn = wid >> 2;
    int kq = tid & 7, rr = tid >> 3;
    int kk = tid & 31, ng = tid >> 5;

    float acc[2][8][4];
#pragma unroll
    for (int mt = 0; mt < 2; mt++)
#pragma unroll
        for (int nt = 0; nt < 8; nt++)
#pragma unroll
            for (int e = 0; e < 4; e++) acc[mt][nt][e] = 0.0f;

    int at_r = (lane & 7) + ((lane >> 3) & 1) * 8;
    int at_k = (lane >> 4) * 8;
    int bt_n = (lane & 7) + ((lane & 16) ? 8 : 0);
    int bt_k = ((lane >> 3) & 1) * 8;

    auto stage = [&](int c, int st) {
        int j0 = c * 32;
        __half* Ah = smh + st * 2 * SARR;
#pragma unroll
        for (int i = 0; i < 4; i++) {
            int r = rr + i * 32;
            *(uint2*)(Ah + r * SPITCH + kq * 4) =
                *(const uint2*)(g_S + ((size_t)b * NB + r0 + r) * NB + j0 + kq * 4);
        }
        __half* Bh = Ah + SARR;
#pragma unroll
        for (int j = 0; j < 4; j++) {
            int n0 = ng * 16 + j * 4;
            union { __half h[4]; uint2 u; } rawv;
            rawv.u = *(const uint2*)(g_v + ((size_t)(b * NB + j0 + kk)) * MCH + d0 + n0);
#pragma unroll
            for (int e = 0; e < 4; e++)
                Bh[(n0 + e) * SPITCH + kk] = rawv.h[e];
        }
    };

    stage(0, 0);
    __syncthreads();
    for (int c = 0; c < 8; c++) {
        int st = c & 1;
        if (c + 1 < 8) stage(c + 1, st ^ 1);
        mma_chunk_h<SPITCH, 2>(smh + st * 2 * SARR, acc, wm, wn, at_r, at_k, bt_n, bt_k);
        __syncthreads();
    }

    int tr = lane >> 2, tc = (lane & 3) * 2;
#pragma unroll
    for (int mt = 0; mt < 2; mt++) {
#pragma unroll
        for (int half = 0; half < 2; half++) {
            int node = b * NB + r0 + wm * 32 + mt * 16 + tr + half * 8;
            bool mk = gmask[bseg[node]] != 0;
#pragma unroll
            for (int nt = 0; nt < 8; nt++) {
                int col = wn * 64 + nt * 8 + tc;
                float o0 = mk ? acc[mt][nt][half * 2 + 0] : 0.0f;
                float o1 = mk ? acc[mt][nt][half * 2 + 1] : 0.0f;
                *(float2*)(out + (size_t)node * MCH + d0 + col) = make_float2(o0, o1);
            }
        }
    }
}

// ---------------- launcher ----------------------------------------------------
extern "C" void kernel_launch(void* const* d_in, const int* in_sizes, int n_in,
                              void* d_out, int out_size) {
    const float* X   = (const float*)d_in[0];
    const float* pos = (const float*)d_in[1];
    const int* bseg  = (const int*)d_in[2];
    const int* gmask = (const int*)d_in[3];   // bool -> int32 in harness
    const float* Wq = (const float*)d_in[4];
    const float* bq = (const float*)d_in[5];
    const float* Wk = (const float*)d_in[6];
    const float* bk = (const float*)d_in[7];
    const float* Wv = (const float*)d_in[8];
    const float* bv = (const float*)d_in[9];
    float* out = (float*)d_out;

    cudaFuncSetAttribute(k_proj,  cudaFuncAttributeMaxDynamicSharedMemorySize, PO_SMEM);
    cudaFuncSetAttribute(k_score, cudaFuncAttributeMaxDynamicSharedMemorySize, KS_SMEM);
    cudaFuncSetAttribute(k_out,   cudaFuncAttributeMaxDynamicSharedMemorySize, PO_SMEM);

    const int NPRE = NN * 3 * 32 + 9 * 128 * 64;
    k_pre<<<(NPRE + 255) / 256, 256>>>(pos, Wq, Wk, Wv);
    k_proj<<<dim3(160, 1, 9), 256, PO_SMEM>>>(X, bq, bk, bv);
    k_score<<<dim3(2, 2, BB * 9), 256, KS_SMEM>>>();
    k_reduceS<<<SZSLAB / 2048, 256>>>();
    k_out<<<dim3(2, 9, BB), 256, PO_SMEM>>>(bseg, gmask, out);
}